// round 15
// baseline (speedup 1.0000x reference)
#include <cuda_runtime.h>
#include <cstdint>

// GAE reverse scan — FINAL (R13 configuration, the measured optimum).
//
// adv[t] = (r[t] + GAMMA*V[t+1] - V[t]) + GAMMA*LAMBDA*adv[t+1], exact scan.
// Single-chunk cp.async SMEM pipeline: 201.4MB mandatory traffic moved at
// 7.28 TB/s effective (91% of 8TB/s spec), kernel 27.7us, rel_err 9.8e-8.
//
// Every axis bracketed by experiment; neighbors regress:
//  - buffering: SMEM cp.async >> register buffers (RF caps in-flight at ~55%)
//  - time split: none. Halo splits cost LTS bytes even when L2-absorbed
//    (2-way: 222MB issued @ LTS cap; 4-way: L2 eviction, 62% DRAM)
//  - block shape: NCOL=64 (2 warps, warp-private 32-col halves)
//  - ring: DEPTH=8 (64KB smem; 5/6 shallower and 12 deeper both slower)
//  - ordering: wait_group -> refill -> consume (fill-first regressed)
//  - stores: st.global.cs (streaming, no L2 pollution)

#define T_DIM    1024
#define B_DIM    16384
#define GAMMA    0.99f
#define COEF     (0.99f * 0.97f)
#define UNR      16          // time rows per stage
#define NCOL     64          // columns per block (two warps, warp-private 32)
#define DEPTH    8           // ring stages (64KB static smem, 7 in flight)
#define NSTAGES  64          // 1024 / UNR

__device__ __forceinline__ uint32_t smem_u32(const void* p) {
    return (uint32_t)__cvta_generic_to_shared(p);
}

// Fill stage k_: warp w copies rows 0..15 x columns [32w,32w+32) of v and r.
// Per thread 4 float4 per array: row = lane/8 + 4j, col = 32w + (lane&7)*4.
#define FILL_STAGE(k_)                                                        \
    {                                                                         \
        const int ts_   = T_DIM - UNR * ((k_) + 1);                           \
        const int slot_ = (k_) % DEPTH;                                       \
        const uint32_t svb = smem_u32(&sv[slot_][0]);                         \
        const uint32_t srb = smem_u32(&sr[slot_][0]);                         \
        _Pragma("unroll")                                                     \
        for (int j = 0; j < 4; j++) {                                         \
            const int row  = (lane >> 3) + 4 * j;                             \
            const int col  = wbase + (lane & 7) * 4;                          \
            const int flat = row * NCOL + col;     /* float index in tile */  \
            const size_t g = (size_t)(ts_ + row) * B_DIM + cb + col;          \
            asm volatile("cp.async.cg.shared.global [%0], [%1], 16;"          \
                         :: "r"(svb + flat * 4), "l"(value + g));             \
            asm volatile("cp.async.cg.shared.global [%0], [%1], 16;"          \
                         :: "r"(srb + flat * 4), "l"(reward + g));            \
        }                                                                     \
    }

__global__ void __launch_bounds__(NCOL) gae_kernel(
    const float* __restrict__ value,   // (T+1, B)
    const float* __restrict__ reward,  // (T, B)
    float* __restrict__ adv)           // (T, B)
{
    __shared__ float sv[DEPTH][UNR * NCOL];   // 32KB
    __shared__ float sr[DEPTH][UNR * NCOL];   // 32KB

    const int tid   = threadIdx.x;
    const int lane  = tid & 31;
    const int wbase = tid & 32;               // 0 or 32: this warp's column base
    const int cb    = blockIdx.x * NCOL;
    const int b     = cb + tid;

    float carry  = 0.0f;                       // exact: scan starts at t = T
    float v_next = value[(size_t)T_DIM * B_DIM + b];

    // Prologue: DEPTH-1 stages in flight before any compute.
    #pragma unroll
    for (int s = 0; s < DEPTH - 1; s++) {
        FILL_STAGE(s);
        asm volatile("cp.async.commit_group;");
    }

    for (int k = 0; k < NSTAGES; k++) {
        // Stage k complete when <= DEPTH-2 of this warp's groups pending.
        asm volatile("cp.async.wait_group %0;" :: "n"(DEPTH - 2));
        __syncwarp();   // columns are warp-private: intra-warp visibility only

        // Refill the slot freed by stage k-1 (this warp's own columns).
        if (k + DEPTH - 1 < NSTAGES) {
            FILL_STAGE(k + DEPTH - 1);
        }
        asm volatile("cp.async.commit_group;");   // empty tail groups keep counts aligned

        // Consume stage k: time descending within the stage.
        const int slot = k % DEPTH;
        const int ts   = T_DIM - UNR * (k + 1);
        #pragma unroll
        for (int j = UNR - 1; j >= 0; j--) {
            const float vt = sv[slot][j * NCOL + tid];
            const float rt = sr[slot][j * NCOL + tid];
            const float delta = fmaf(GAMMA, v_next, rt) - vt;
            carry = fmaf(COEF, carry, delta);
            __stcs(&adv[(size_t)(ts + j) * B_DIM + b], carry);  // streaming write
            v_next = vt;
        }
        __syncwarp();
    }
}

extern "C" void kernel_launch(void* const* d_in, const int* in_sizes, int n_in,
                              void* d_out, int out_size)
{
    const float* value  = (const float*)d_in[0];
    const float* reward = (const float*)d_in[1];
    float* adv = (float*)d_out;

    gae_kernel<<<B_DIM / NCOL, NCOL>>>(value, reward, adv);   // 256 blocks
}

// round 16
// speedup vs baseline: 1.0626x; 1.0626x over previous
#include <cuda_runtime.h>
#include <cstdint>

// GAE reverse scan — FINAL (R13 configuration, the measured optimum).
//
// adv[t] = (r[t] + GAMMA*V[t+1] - V[t]) + GAMMA*LAMBDA*adv[t+1], exact scan.
// Single-chunk cp.async SMEM pipeline: 201.4MB mandatory traffic, best
// measured 27.7us kernel = 7.28 TB/s effective (91% of 8TB/s spec),
// rel_err 9.8e-8. R13 vs R15 (identical source) bracketed run-to-run noise
// at +/-2us; all post-R13 restructurings regressed by real signal.
//
// Every axis bracketed by experiment; neighbors regress:
//  - buffering: SMEM cp.async >> register buffers (RF caps in-flight, ~55% DRAM)
//  - time split: none. Halo splits cost LTS bytes even when L2-absorbed
//    (2-way: 222MB issued @ the ~6300 B/cyc LTS cap; 4-way: L2 eviction)
//  - block shape: NCOL=64 (2 warps, warp-private 32-col halves, __syncwarp)
//  - ring: DEPTH=8 (64KB smem; 5/6 shallower and 12 deeper both slower)
//  - ordering: wait_group -> refill -> consume (fill-first regressed)
//  - stores: st.global.cs (streaming, no L2 pollution)

#define T_DIM    1024
#define B_DIM    16384
#define GAMMA    0.99f
#define COEF     (0.99f * 0.97f)
#define UNR      16          // time rows per stage
#define NCOL     64          // columns per block (two warps, warp-private 32)
#define DEPTH    8           // ring stages (64KB static smem, 7 in flight)
#define NSTAGES  64          // 1024 / UNR

__device__ __forceinline__ uint32_t smem_u32(const void* p) {
    return (uint32_t)__cvta_generic_to_shared(p);
}

// Fill stage k_: warp w copies rows 0..15 x columns [32w,32w+32) of v and r.
// Per thread 4 float4 per array: row = lane/8 + 4j, col = 32w + (lane&7)*4.
#define FILL_STAGE(k_)                                                        \
    {                                                                         \
        const int ts_   = T_DIM - UNR * ((k_) + 1);                           \
        const int slot_ = (k_) % DEPTH;                                       \
        const uint32_t svb = smem_u32(&sv[slot_][0]);                         \
        const uint32_t srb = smem_u32(&sr[slot_][0]);                         \
        _Pragma("unroll")                                                     \
        for (int j = 0; j < 4; j++) {                                         \
            const int row  = (lane >> 3) + 4 * j;                             \
            const int col  = wbase + (lane & 7) * 4;                          \
            const int flat = row * NCOL + col;     /* float index in tile */  \
            const size_t g = (size_t)(ts_ + row) * B_DIM + cb + col;          \
            asm volatile("cp.async.cg.shared.global [%0], [%1], 16;"          \
                         :: "r"(svb + flat * 4), "l"(value + g));             \
            asm volatile("cp.async.cg.shared.global [%0], [%1], 16;"          \
                         :: "r"(srb + flat * 4), "l"(reward + g));            \
        }                                                                     \
    }

__global__ void __launch_bounds__(NCOL) gae_kernel(
    const float* __restrict__ value,   // (T+1, B)
    const float* __restrict__ reward,  // (T, B)
    float* __restrict__ adv)           // (T, B)
{
    __shared__ float sv[DEPTH][UNR * NCOL];   // 32KB
    __shared__ float sr[DEPTH][UNR * NCOL];   // 32KB

    const int tid   = threadIdx.x;
    const int lane  = tid & 31;
    const int wbase = tid & 32;               // 0 or 32: this warp's column base
    const int cb    = blockIdx.x * NCOL;
    const int b     = cb + tid;

    float carry  = 0.0f;                       // exact: scan starts at t = T
    float v_next = value[(size_t)T_DIM * B_DIM + b];

    // Prologue: DEPTH-1 stages in flight before any compute.
    #pragma unroll
    for (int s = 0; s < DEPTH - 1; s++) {
        FILL_STAGE(s);
        asm volatile("cp.async.commit_group;");
    }

    for (int k = 0; k < NSTAGES; k++) {
        // Stage k complete when <= DEPTH-2 of this warp's groups pending.
        asm volatile("cp.async.wait_group %0;" :: "n"(DEPTH - 2));
        __syncwarp();   // columns are warp-private: intra-warp visibility only

        // Refill the slot freed by stage k-1 (this warp's own columns).
        if (k + DEPTH - 1 < NSTAGES) {
            FILL_STAGE(k + DEPTH - 1);
        }
        asm volatile("cp.async.commit_group;");   // empty tail groups keep counts aligned

        // Consume stage k: time descending within the stage.
        const int slot = k % DEPTH;
        const int ts   = T_DIM - UNR * (k + 1);
        #pragma unroll
        for (int j = UNR - 1; j >= 0; j--) {
            const float vt = sv[slot][j * NCOL + tid];
            const float rt = sr[slot][j * NCOL + tid];
            const float delta = fmaf(GAMMA, v_next, rt) - vt;
            carry = fmaf(COEF, carry, delta);
            __stcs(&adv[(size_t)(ts + j) * B_DIM + b], carry);  // streaming write
            v_next = vt;
        }
        __syncwarp();
    }
}

extern "C" void kernel_launch(void* const* d_in, const int* in_sizes, int n_in,
                              void* d_out, int out_size)
{
    const float* value  = (const float*)d_in[0];
    const float* reward = (const float*)d_in[1];
    float* adv = (float*)d_out;

    gae_kernel<<<B_DIM / NCOL, NCOL>>>(value, reward, adv);   // 256 blocks
}